// round 1
// baseline (speedup 1.0000x reference)
#include <cuda_runtime.h>
#include <math.h>

#define Bc 4
#define Sc 2048
#define Ec 1024
#define Hc 8
#define Dc 128
#define BSc (Bc*Sc)        // 8192 tokens
#define HDc (Hc*Dc)        // 1024
#define EPSc 1e-5f

// ---------------- scratch (static device arrays; no allocation allowed) ----------------
__device__ __align__(16) float g_z   [BSc*HDc];   // tanh(x@W_ez+b)   [B,S,H*D]
__device__ __align__(16) float g_hln [BSc*HDc];   // post ff-LN states [B,S,H*D]
__device__ __align__(16) float g_h1  [BSc*HDc];   // gelu(hln@W1+b1), later scaled by scores in-place
__device__ __align__(16) float g_sc  [BSc*Hc];    // softmax scores
__device__ __align__(16) float g_v   [HDc];       // v_h = ff_W2[h] @ w_att
__device__ __align__(16) float g_c   [Hc];        // c_h = b2[h] . w_att

// ---------------- helpers ----------------
__device__ __forceinline__ float warpSum(float v){
    #pragma unroll
    for (int o = 16; o; o >>= 1) v += __shfl_xor_sync(0xffffffffu, v, o);
    return v;
}
__device__ __forceinline__ void warpRed4(float& a, float& b, float& c, float& d){
    #pragma unroll
    for (int o = 16; o; o >>= 1){
        a += __shfl_xor_sync(0xffffffffu, a, o);
        b += __shfl_xor_sync(0xffffffffu, b, o);
        c += __shfl_xor_sync(0xffffffffu, c, o);
        d += __shfl_xor_sync(0xffffffffu, d, o);
    }
}

// ---------------- K0: precompute v_h (W2[h]@w_att) and c_h (b2[h].w_att) ----------------
// grid = HDc + Hc blocks, 256 threads; each block reduces a length-1024 dot.
__global__ void k_prep(const float* __restrict__ W2, const float* __restrict__ b2,
                       const float* __restrict__ watt){
    int idx = blockIdx.x;
    const float* row = (idx < HDc) ? (W2 + (size_t)idx * Ec)
                                   : (b2 + (size_t)(idx - HDc) * Ec);
    int t = threadIdx.x;
    float4 a = ((const float4*)row)[t];
    float4 w = ((const float4*)watt)[t];
    float p = a.x*w.x + a.y*w.y + a.z*w.z + a.w*w.w;
    p = warpSum(p);
    __shared__ float sh[8];
    if ((t & 31) == 0) sh[t >> 5] = p;
    __syncthreads();
    if (t == 0){
        float r = 0.f;
        #pragma unroll
        for (int i = 0; i < 8; i++) r += sh[i];
        if (idx < HDc) g_v[idx] = r; else g_c[idx - HDc] = r;
    }
}

// ---------------- generic fp32 GEMM, 128x128 block tile, 8x8/thread ----------------
// C[m,n] = sum_k A[m,k]*B[k,n]  (+ epilogue)
// EPI 0: tanh(acc + bias[n])           -> z
// EPI 1: gelu(acc + bias[n])           -> h1
// EPI 2: acc + sum_h scores[m,h]*bias[h*Ec+n]   -> pre-LN output
template<int EPI>
__global__ void __launch_bounds__(256, 2) k_gemm(
    const float* __restrict__ A, int lda, long sA,
    const float* __restrict__ Bm, int ldb, long sB,
    float* __restrict__ C, int ldc, long sC,
    int K,
    const float* __restrict__ bias, long sBias,
    const float* __restrict__ scores)
{
    __shared__ float As[16][128];
    __shared__ float Bs[16][128];

    int z = blockIdx.z;
    A  += (size_t)z * sA;
    Bm += (size_t)z * sB;
    C  += (size_t)z * sC;
    const float* bi = bias + (size_t)z * sBias;

    const int m0 = blockIdx.y * 128;
    const int n0 = blockIdx.x * 128;
    const int tid = threadIdx.x;
    const int tx = tid & 15, ty = tid >> 4;

    const int arow = tid >> 2;           // 0..63
    const int acol = (tid & 3) * 4;      // 0,4,8,12
    const int brow = tid >> 5;           // 0..7
    const int bcol = (tid & 31) * 4;     // 0..124

    float acc[8][8];
    #pragma unroll
    for (int i = 0; i < 8; i++)
        #pragma unroll
        for (int j = 0; j < 8; j++) acc[i][j] = 0.f;

    for (int kt = 0; kt < K; kt += 16){
        float4 a0 = *(const float4*)(A + (size_t)(m0 + arow      ) * lda + kt + acol);
        float4 a1 = *(const float4*)(A + (size_t)(m0 + arow + 64 ) * lda + kt + acol);
        float4 b0 = *(const float4*)(Bm + (size_t)(kt + brow    ) * ldb + n0 + bcol);
        float4 b1 = *(const float4*)(Bm + (size_t)(kt + brow + 8) * ldb + n0 + bcol);
        __syncthreads();
        As[acol + 0][arow] = a0.x; As[acol + 1][arow] = a0.y;
        As[acol + 2][arow] = a0.z; As[acol + 3][arow] = a0.w;
        As[acol + 0][arow + 64] = a1.x; As[acol + 1][arow + 64] = a1.y;
        As[acol + 2][arow + 64] = a1.z; As[acol + 3][arow + 64] = a1.w;
        *(float4*)&Bs[brow    ][bcol] = b0;
        *(float4*)&Bs[brow + 8][bcol] = b1;
        __syncthreads();
        #pragma unroll
        for (int k = 0; k < 16; k++){
            float a[8], b[8];
            #pragma unroll
            for (int i = 0; i < 8; i++) a[i] = As[k][ty + 16*i];
            #pragma unroll
            for (int j = 0; j < 8; j++) b[j] = Bs[k][tx + 16*j];
            #pragma unroll
            for (int i = 0; i < 8; i++)
                #pragma unroll
                for (int j = 0; j < 8; j++)
                    acc[i][j] = fmaf(a[i], b[j], acc[i][j]);
        }
    }

    if (EPI == 2){
        float scr[8][8];   // [row i][head]
        #pragma unroll
        for (int i = 0; i < 8; i++){
            int m = m0 + ty + 16*i;
            #pragma unroll
            for (int hh = 0; hh < 8; hh++) scr[i][hh] = scores[m*8 + hh];
        }
        float b2v[8][8];   // [head][col j]
        #pragma unroll
        for (int hh = 0; hh < 8; hh++)
            #pragma unroll
            for (int j = 0; j < 8; j++)
                b2v[hh][j] = bi[hh*Ec + n0 + tx + 16*j];
        #pragma unroll
        for (int i = 0; i < 8; i++){
            float* crow = C + (size_t)(m0 + ty + 16*i) * ldc + n0;
            #pragma unroll
            for (int j = 0; j < 8; j++){
                float s = acc[i][j];
                #pragma unroll
                for (int hh = 0; hh < 8; hh++) s = fmaf(scr[i][hh], b2v[hh][j], s);
                crow[tx + 16*j] = s;
            }
        }
    } else {
        float bv[8];
        #pragma unroll
        for (int j = 0; j < 8; j++) bv[j] = bi[n0 + tx + 16*j];
        #pragma unroll
        for (int i = 0; i < 8; i++){
            float* crow = C + (size_t)(m0 + ty + 16*i) * ldc + n0;
            #pragma unroll
            for (int j = 0; j < 8; j++){
                float t = acc[i][j] + bv[j];
                if (EPI == 0) t = tanhf(t);
                else          t = 0.5f * t * (1.0f + erff(t * 0.70710678118654752f));
                crow[tx + 16*j] = t;
            }
        }
    }
}

// ---------------- scan: 32 blocks (one per (b,h)), 32 threads; state in registers ----------------
__global__ void k_scan(const float* __restrict__ Uh, const float* __restrict__ Uz,
                       const float* __restrict__ bu, const float* __restrict__ os,
                       const float* __restrict__ lnsg, const float* __restrict__ lnsb,
                       const float* __restrict__ ffg, const float* __restrict__ ffb)
{
    const int bh = blockIdx.x;
    const int b = bh >> 3, h = bh & 7;
    const int l = threadIdx.x;

    float uh[4], uz[4], bub[4], osd[4], g1[4], bb1[4], g2[4], bb2[4];
    #pragma unroll
    for (int k = 0; k < 4; k++){
        int d = l*4 + k;
        uh[k]  = Uh[h*Dc*Dc + d*(Dc + 1)];       // diagonal
        uz[k]  = Uz[h*Dc*Dc + d*(Dc + 1)];
        osd[k] = os[h*Dc*Dc + d*(Dc + 1)];
        bub[k] = bu[h*Dc + d];
        g1[k]  = lnsg[d];        bb1[k] = lnsb[d];
        g2[k]  = ffg[h*Dc + d];  bb2[k] = ffb[h*Dc + d];
    }

    const float4* zp = (const float4*)g_z  + (size_t)b*Sc*256 + h*32 + l;
    float4*       op = (float4*)g_hln      + (size_t)b*Sc*256 + h*32 + l;

    float hst[4] = {0.f, 0.f, 0.f, 0.f};
    float sh [4] = {0.f, 0.f, 0.f, 0.f};   // shaped values of previous step (pending ff-LN)
    float4 zc = *zp;

    for (int s = 0; s < Sc; s++){
        float4 zn = {0.f,0.f,0.f,0.f};
        if (s + 1 < Sc) zn = zp[(size_t)(s + 1) * 256];

        float zv[4] = {zc.x, zc.y, zc.z, zc.w};
        float hn[4];
        float s1 = 0.f, s2 = 0.f;
        #pragma unroll
        for (int k = 0; k < 4; k++){
            float t = fmaf(hst[k], uh[k], fmaf(zv[k], uz[k], bub[k]));
            float u = __fdividef(1.f, 1.f + __expf(-t));
            float v = fmaf(u, hst[k] - zv[k], zv[k]);   // u*h + (1-u)*z
            hn[k] = v;
            s1 += v;
            s2 = fmaf(v, v, s2);
        }
        float t1 = 0.f, t2 = 0.f;
        #pragma unroll
        for (int k = 0; k < 4; k++){ t1 += sh[k]; t2 = fmaf(sh[k], sh[k], t2); }

        warpRed4(s1, s2, t1, t2);   // both LN reductions share one shuffle chain

        if (s > 0){  // finish ff-LN of step s-1 (off the scan critical path)
            float m2 = t1 * (1.f/Dc);
            float vr = t2 * (1.f/Dc) - m2*m2;
            float rs2 = rsqrtf(vr + EPSc);
            float4 o;
            o.x = fmaf((sh[0]-m2)*rs2, g2[0], bb2[0]);
            o.y = fmaf((sh[1]-m2)*rs2, g2[1], bb2[1]);
            o.z = fmaf((sh[2]-m2)*rs2, g2[2], bb2[2]);
            o.w = fmaf((sh[3]-m2)*rs2, g2[3], bb2[3]);
            op[(size_t)(s - 1) * 256] = o;
        }

        float m  = s1 * (1.f/Dc);
        float vr = s2 * (1.f/Dc) - m*m;
        float rs = rsqrtf(vr + EPSc);
        #pragma unroll
        for (int k = 0; k < 4; k++){
            float v = fmaf((hn[k]-m)*rs, g1[k], bb1[k]);  // state LN
            hst[k] = v;
            sh[k]  = v * osd[k];                           // shaped for ff-LN
        }
        zc = zn;
    }
    // flush last step's ff-LN
    {
        float t1 = 0.f, t2 = 0.f, d1 = 0.f, d2 = 0.f;
        #pragma unroll
        for (int k = 0; k < 4; k++){ t1 += sh[k]; t2 = fmaf(sh[k], sh[k], t2); }
        warpRed4(t1, t2, d1, d2);
        float m2 = t1 * (1.f/Dc);
        float vr = t2 * (1.f/Dc) - m2*m2;
        float rs2 = rsqrtf(vr + EPSc);
        float4 o;
        o.x = fmaf((sh[0]-m2)*rs2, g2[0], bb2[0]);
        o.y = fmaf((sh[1]-m2)*rs2, g2[1], bb2[1]);
        o.z = fmaf((sh[2]-m2)*rs2, g2[2], bb2[2]);
        o.w = fmaf((sh[3]-m2)*rs2, g2[3], bb2[3]);
        op[(size_t)(Sc - 1) * 256] = o;
    }
}

// ---------------- K4: logits -> softmax over heads -> scale h1 in place ----------------
// grid = 8192 blocks, 256 threads (warp w handles head w)
__global__ void k_soft(float* __restrict__ h1, float* __restrict__ scores){
    int row = blockIdx.x;
    int t = threadIdx.x, h = t >> 5, l = t & 31;
    float* base = h1 + (size_t)row * HDc + h * Dc;
    float4 a  = ((float4*)base)[l];
    float4 vv = ((const float4*)(g_v + h * Dc))[l];
    float p = a.x*vv.x + a.y*vv.y + a.z*vv.z + a.w*vv.w;
    p = warpSum(p);
    __shared__ float lg[8];
    if (l == 0) lg[h] = p + g_c[h];
    __syncthreads();
    float mx = lg[0];
    #pragma unroll
    for (int i = 1; i < 8; i++) mx = fmaxf(mx, lg[i]);
    float den = 0.f;
    #pragma unroll
    for (int i = 0; i < 8; i++) den += __expf(lg[i] - mx);
    float sc = __expf(lg[h] - mx) / den;
    a.x *= sc; a.y *= sc; a.z *= sc; a.w *= sc;
    ((float4*)base)[l] = a;
    if (l == 0) scores[row*Hc + h] = sc;
}

// ---------------- K6: output LayerNorm over E, in-place on d_out ----------------
__global__ void k_outln(float* __restrict__ out,
                        const float* __restrict__ g, const float* __restrict__ bta){
    int row = blockIdx.x;
    int t = threadIdx.x;
    float4* p = (float4*)(out + (size_t)row * Ec);
    float4 v = p[t];
    float s1 = v.x + v.y + v.z + v.w;
    float s2 = v.x*v.x + v.y*v.y + v.z*v.z + v.w*v.w;
    s1 = warpSum(s1); s2 = warpSum(s2);
    __shared__ float sh1[8], sh2[8];
    if ((t & 31) == 0){ sh1[t >> 5] = s1; sh2[t >> 5] = s2; }
    __syncthreads();
    if (t < 32){
        float a = (t < 8) ? sh1[t] : 0.f;
        float b = (t < 8) ? sh2[t] : 0.f;
        a = warpSum(a); b = warpSum(b);
        if (t == 0){ sh1[0] = a; sh2[0] = b; }
    }
    __syncthreads();
    float mean = sh1[0] * (1.f/Ec);
    float var  = sh2[0] * (1.f/Ec) - mean*mean;
    float rs = rsqrtf(var + EPSc);
    float4 gg = ((const float4*)g  )[t];
    float4 bb = ((const float4*)bta)[t];
    float4 o;
    o.x = fmaf((v.x-mean)*rs, gg.x, bb.x);
    o.y = fmaf((v.y-mean)*rs, gg.y, bb.y);
    o.z = fmaf((v.z-mean)*rs, gg.z, bb.z);
    o.w = fmaf((v.w-mean)*rs, gg.w, bb.w);
    p[t] = o;
}

// ---------------- launch ----------------
extern "C" void kernel_launch(void* const* d_in, const int* in_sizes, int n_in,
                              void* d_out, int out_size)
{
    const float* x    = (const float*)d_in[0];
    const float* Wez  = (const float*)d_in[1];
    const float* bez  = (const float*)d_in[2];
    const float* Uh   = (const float*)d_in[3];
    const float* Uz   = (const float*)d_in[4];
    const float* bu   = (const float*)d_in[5];
    const float* os   = (const float*)d_in[6];
    const float* lnsg = (const float*)d_in[7];
    const float* lnsb = (const float*)d_in[8];
    const float* ffg  = (const float*)d_in[9];
    const float* ffb  = (const float*)d_in[10];
    const float* W1   = (const float*)d_in[11];
    const float* b1   = (const float*)d_in[12];
    const float* W2   = (const float*)d_in[13];
    const float* b2   = (const float*)d_in[14];
    const float* watt = (const float*)d_in[15];
    const float* lnog = (const float*)d_in[17];
    const float* lnob = (const float*)d_in[18];
    float* out = (float*)d_out;

    float *z, *hln, *h1, *sc;
    cudaGetSymbolAddress((void**)&z,   g_z);
    cudaGetSymbolAddress((void**)&hln, g_hln);
    cudaGetSymbolAddress((void**)&h1,  g_h1);
    cudaGetSymbolAddress((void**)&sc,  g_sc);

    // K0: v_h, c_h
    k_prep<<<HDc + Hc, 256>>>(W2, b2, watt);
    // GEMM1: z = tanh(x @ W_ez + b_ez)
    k_gemm<0><<<dim3(HDc/128, BSc/128, 1), 256>>>(x, Ec, 0, Wez, HDc, 0,
                                                  z, HDc, 0, Ec, bez, 0, nullptr);
    // scan (reads g_z, writes g_hln)
    k_scan<<<32, 32>>>(Uh, Uz, bu, os, lnsg, lnsb, ffg, ffb);
    // GEMM2 per head: h1 = gelu(hln @ W1[h] + b1[h])
    k_gemm<1><<<dim3(1, BSc/128, Hc), 256>>>(hln, HDc, Dc, W1, Dc, (long)Dc*Dc,
                                             h1, HDc, Dc, Dc, b1, Dc, nullptr);
    // softmax over heads, scale h1 -> g in place
    k_soft<<<BSc, 256>>>(h1, sc);
    // GEMM3: out_pre = g @ W2_stacked + sum_h scores*b2[h]
    k_gemm<2><<<dim3(Ec/128, BSc/128, 1), 256>>>(h1, HDc, 0, W2, Ec, 0,
                                                 out, Ec, 0, HDc, b2, 0, sc);
    // final LN in-place
    k_outln<<<BSc, 256>>>(out, lnog, lnob);
}

// round 2
// speedup vs baseline: 1.4526x; 1.4526x over previous
#include <cuda_runtime.h>
#include <math.h>

#define Bc 4
#define Sc 2048
#define Ec 1024
#define Hc 8
#define Dc 128
#define BSc (Bc*Sc)        // 8192 tokens
#define HDc (Hc*Dc)        // 1024
#define EPSc 1e-5f

// ---------------- scratch ----------------
__device__ __align__(16) float g_z   [BSc*HDc];
__device__ __align__(16) float g_hln [BSc*HDc];
__device__ __align__(16) float g_h1  [BSc*HDc];
__device__ __align__(16) float g_sc  [BSc*Hc];
__device__ __align__(16) float g_v   [HDc];
__device__ __align__(16) float g_c   [Hc];

// ---------------- helpers ----------------
__device__ __forceinline__ float warpSum(float v){
    #pragma unroll
    for (int o = 16; o; o >>= 1) v += __shfl_xor_sync(0xffffffffu, v, o);
    return v;
}
__device__ __forceinline__ void warpRed4(float& a, float& b, float& c, float& d){
    #pragma unroll
    for (int o = 16; o; o >>= 1){
        a += __shfl_xor_sync(0xffffffffu, a, o);
        b += __shfl_xor_sync(0xffffffffu, b, o);
        c += __shfl_xor_sync(0xffffffffu, c, o);
        d += __shfl_xor_sync(0xffffffffu, d, o);
    }
}
__device__ __forceinline__ float f2tf(float f){
    unsigned r; asm("cvt.rna.tf32.f32 %0, %1;" : "=r"(r) : "f"(f));
    return __uint_as_float(r);
}
__device__ __forceinline__ void mma8(float* c, const unsigned* a, const unsigned* b){
    asm volatile("mma.sync.aligned.m16n8k8.row.col.f32.tf32.tf32.f32 "
        "{%0,%1,%2,%3}, {%4,%5,%6,%7}, {%8,%9}, {%0,%1,%2,%3};"
        : "+f"(c[0]), "+f"(c[1]), "+f"(c[2]), "+f"(c[3])
        : "r"(a[0]), "r"(a[1]), "r"(a[2]), "r"(a[3]), "r"(b[0]), "r"(b[1]));
}

// ---------------- K0: precompute v_h, c_h ----------------
__global__ void k_prep(const float* __restrict__ W2, const float* __restrict__ b2,
                       const float* __restrict__ watt){
    int idx = blockIdx.x;
    const float* row = (idx < HDc) ? (W2 + (size_t)idx * Ec)
                                   : (b2 + (size_t)(idx - HDc) * Ec);
    int t = threadIdx.x;
    float4 a = ((const float4*)row)[t];
    float4 w = ((const float4*)watt)[t];
    float p = a.x*w.x + a.y*w.y + a.z*w.z + a.w*w.w;
    p = warpSum(p);
    __shared__ float sh[8];
    if ((t & 31) == 0) sh[t >> 5] = p;
    __syncthreads();
    if (t == 0){
        float r = 0.f;
        #pragma unroll
        for (int i = 0; i < 8; i++) r += sh[i];
        if (idx < HDc) g_v[idx] = r; else g_c[idx - HDc] = r;
    }
}

// ---------------- TF32 tensor-core GEMM ----------------
// 128x128 block, BK=16, 256 threads, 8 warps in 2(m) x 4(n); warp tile 64x32.
// EPI 0: tanh(acc+bias[n]); EPI 1: gelu(acc+bias[n]);
// EPI 2: acc + sum_h scores[m,h]*bias[h*Ec+n]
template<int EPI>
__global__ void __launch_bounds__(256, 2) k_gemm_tc(
    const float* __restrict__ A, int lda, long strA,
    const float* __restrict__ Bm, int ldb, long strB,
    float* __restrict__ C, int ldc, long strC,
    int K,
    const float* __restrict__ bias, long strBias,
    const float* __restrict__ scores)
{
    __shared__ float As[2][128][20];
    __shared__ float Bs[2][16][136];

    const int zb = blockIdx.z;
    A  += (size_t)zb * strA;
    Bm += (size_t)zb * strB;
    C  += (size_t)zb * strC;
    const float* bi = bias + (size_t)zb * strBias;

    const int m0 = blockIdx.y * 128;
    const int n0 = blockIdx.x * 128;
    const int tid = threadIdx.x;
    const int l  = tid & 31;
    const int lq = l >> 2;        // 0..7
    const int lr = l & 3;         // 0..3
    const int wm = (tid >> 5) & 1;
    const int wn = tid >> 6;      // 0..3

    // global load mapping
    const int arow = tid >> 1;            // 0..127
    const int acol = (tid & 1) * 8;       // 0 or 8
    const int brow = tid >> 4;            // 0..15
    const int bcol = (tid & 15) * 8;      // 0..120

    const float* Aq = A + (size_t)(m0 + arow) * lda + acol;
    const float* Bq = Bm + (size_t)brow * ldb + n0 + bcol;

    float acc[4][4][4];
    #pragma unroll
    for (int i = 0; i < 4; i++)
        #pragma unroll
        for (int j = 0; j < 4; j++)
            #pragma unroll
            for (int k = 0; k < 4; k++) acc[i][j][k] = 0.f;

    float4 ra0, ra1, rb0, rb1;
    ra0 = *(const float4*)(Aq);     ra1 = *(const float4*)(Aq + 4);
    rb0 = *(const float4*)(Bq);     rb1 = *(const float4*)(Bq + 4);

    const int nk = K >> 4;

    // store tile 0
    {
        float* pa = &As[0][arow][acol];
        pa[0]=f2tf(ra0.x); pa[1]=f2tf(ra0.y); pa[2]=f2tf(ra0.z); pa[3]=f2tf(ra0.w);
        pa[4]=f2tf(ra1.x); pa[5]=f2tf(ra1.y); pa[6]=f2tf(ra1.z); pa[7]=f2tf(ra1.w);
        float* pb = &Bs[0][brow][bcol];
        pb[0]=f2tf(rb0.x); pb[1]=f2tf(rb0.y); pb[2]=f2tf(rb0.z); pb[3]=f2tf(rb0.w);
        pb[4]=f2tf(rb1.x); pb[5]=f2tf(rb1.y); pb[6]=f2tf(rb1.z); pb[7]=f2tf(rb1.w);
    }
    __syncthreads();

    for (int kt = 0; kt < nk; kt++){
        const int cur = kt & 1;
        if (kt + 1 < nk){
            const float* Aq2 = Aq + (kt + 1) * 16;
            const float* Bq2 = Bq + (size_t)(kt + 1) * 16 * ldb;
            ra0 = *(const float4*)(Aq2);     ra1 = *(const float4*)(Aq2 + 4);
            rb0 = *(const float4*)(Bq2);     rb1 = *(const float4*)(Bq2 + 4);
        }
        // compute on buffer cur
        {
            const float (*Ac)[20]  = As[cur];
            const float (*Bt)[136] = Bs[cur];
            #pragma unroll
            for (int k8 = 0; k8 < 2; k8++){
                const int kk = k8 * 8;
                unsigned af[4][4], bf[4][2];
                #pragma unroll
                for (int mt = 0; mt < 4; mt++){
                    const int r0 = wm*64 + mt*16 + lq;
                    af[mt][0] = __float_as_uint(Ac[r0    ][kk + lr]);
                    af[mt][1] = __float_as_uint(Ac[r0 + 8][kk + lr]);
                    af[mt][2] = __float_as_uint(Ac[r0    ][kk + 4 + lr]);
                    af[mt][3] = __float_as_uint(Ac[r0 + 8][kk + 4 + lr]);
                }
                #pragma unroll
                for (int nt = 0; nt < 4; nt++){
                    const int c0 = wn*32 + nt*8 + lq;
                    bf[nt][0] = __float_as_uint(Bt[kk + lr    ][c0]);
                    bf[nt][1] = __float_as_uint(Bt[kk + 4 + lr][c0]);
                }
                #pragma unroll
                for (int mt = 0; mt < 4; mt++)
                    #pragma unroll
                    for (int nt = 0; nt < 4; nt++)
                        mma8(acc[mt][nt], af[mt], bf[nt]);
            }
        }
        __syncthreads();
        if (kt + 1 < nk){
            const int nxt = (kt + 1) & 1;
            float* pa = &As[nxt][arow][acol];
            pa[0]=f2tf(ra0.x); pa[1]=f2tf(ra0.y); pa[2]=f2tf(ra0.z); pa[3]=f2tf(ra0.w);
            pa[4]=f2tf(ra1.x); pa[5]=f2tf(ra1.y); pa[6]=f2tf(ra1.z); pa[7]=f2tf(ra1.w);
            float* pb = &Bs[nxt][brow][bcol];
            pb[0]=f2tf(rb0.x); pb[1]=f2tf(rb0.y); pb[2]=f2tf(rb0.z); pb[3]=f2tf(rb0.w);
            pb[4]=f2tf(rb1.x); pb[5]=f2tf(rb1.y); pb[6]=f2tf(rb1.z); pb[7]=f2tf(rb1.w);
            __syncthreads();
        }
    }

    if (EPI == 2){
        // stage scores[128][8] and b2[8][128] tiles in (reused) smem
        float* scrS = (float*)As;   // 1024 floats
        float* b2S  = (float*)Bs;   // 1024 floats
        for (int i = tid; i < 1024; i += 256)
            scrS[i] = scores[(size_t)(m0 + (i >> 3)) * 8 + (i & 7)];
        for (int i = tid; i < 1024; i += 256)
            b2S[i] = bi[(size_t)(i >> 7) * Ec + n0 + (i & 127)];
        __syncthreads();
        #pragma unroll
        for (int mt = 0; mt < 4; mt++){
            const int rl = wm*64 + mt*16 + lq;     // local row
            #pragma unroll
            for (int nt = 0; nt < 4; nt++){
                const int cl = wn*32 + nt*8 + 2*lr; // local col
                float s0 = acc[mt][nt][0], s1 = acc[mt][nt][1];
                float s2 = acc[mt][nt][2], s3 = acc[mt][nt][3];
                #pragma unroll
                for (int hh = 0; hh < 8; hh++){
                    const float w0 = scrS[rl*8 + hh];
                    const float w1 = scrS[(rl+8)*8 + hh];
                    const float v0 = b2S[hh*128 + cl];
                    const float v1 = b2S[hh*128 + cl + 1];
                    s0 = fmaf(w0, v0, s0); s1 = fmaf(w0, v1, s1);
                    s2 = fmaf(w1, v0, s2); s3 = fmaf(w1, v1, s3);
                }
                float2* p0 = (float2*)(C + (size_t)(m0 + rl) * ldc + n0 + cl);
                float2* p1 = (float2*)(C + (size_t)(m0 + rl + 8) * ldc + n0 + cl);
                *p0 = make_float2(s0, s1);
                *p1 = make_float2(s2, s3);
            }
        }
    } else {
        #pragma unroll
        for (int mt = 0; mt < 4; mt++){
            const int gr = m0 + wm*64 + mt*16 + lq;
            #pragma unroll
            for (int nt = 0; nt < 4; nt++){
                const int gc = n0 + wn*32 + nt*8 + 2*lr;
                const float b0 = bi[gc], b1 = bi[gc + 1];
                float v[4];
                v[0] = acc[mt][nt][0] + b0; v[1] = acc[mt][nt][1] + b1;
                v[2] = acc[mt][nt][2] + b0; v[3] = acc[mt][nt][3] + b1;
                #pragma unroll
                for (int e = 0; e < 4; e++){
                    if (EPI == 0) v[e] = tanhf(v[e]);
                    else          v[e] = 0.5f * v[e] * (1.0f + erff(v[e] * 0.70710678118654752f));
                }
                *(float2*)(C + (size_t)gr * ldc + gc)       = make_float2(v[0], v[1]);
                *(float2*)(C + (size_t)(gr + 8) * ldc + gc) = make_float2(v[2], v[3]);
            }
        }
    }
}

// ---------------- scan: 32 blocks, 32 threads; state in registers ----------------
__global__ void k_scan(const float* __restrict__ Uh, const float* __restrict__ Uz,
                       const float* __restrict__ bu, const float* __restrict__ os,
                       const float* __restrict__ lnsg, const float* __restrict__ lnsb,
                       const float* __restrict__ ffg, const float* __restrict__ ffb)
{
    const int bh = blockIdx.x;
    const int b = bh >> 3, h = bh & 7;
    const int l = threadIdx.x;

    float uh[4], uz[4], bub[4], osd[4], g1[4], bb1[4], g2[4], bb2[4];
    #pragma unroll
    for (int k = 0; k < 4; k++){
        int d = l*4 + k;
        uh[k]  = Uh[h*Dc*Dc + d*(Dc + 1)];
        uz[k]  = Uz[h*Dc*Dc + d*(Dc + 1)];
        osd[k] = os[h*Dc*Dc + d*(Dc + 1)];
        bub[k] = bu[h*Dc + d];
        g1[k]  = lnsg[d];        bb1[k] = lnsb[d];
        g2[k]  = ffg[h*Dc + d];  bb2[k] = ffb[h*Dc + d];
    }

    const float4* zp = (const float4*)g_z  + (size_t)b*Sc*256 + h*32 + l;
    float4*       op = (float4*)g_hln      + (size_t)b*Sc*256 + h*32 + l;

    float hst[4] = {0.f, 0.f, 0.f, 0.f};
    float sh [4] = {0.f, 0.f, 0.f, 0.f};
    float4 zc = *zp;

    for (int s = 0; s < Sc; s++){
        float4 zn = {0.f,0.f,0.f,0.f};
        if (s + 1 < Sc) zn = zp[(size_t)(s + 1) * 256];

        float zv[4] = {zc.x, zc.y, zc.z, zc.w};
        float hn[4];
        float s1 = 0.f, s2 = 0.f;
        #pragma unroll
        for (int k = 0; k < 4; k++){
            float t = fmaf(hst[k], uh[k], fmaf(zv[k], uz[k], bub[k]));
            float u = __fdividef(1.f, 1.f + __expf(-t));
            float v = fmaf(u, hst[k] - zv[k], zv[k]);
            hn[k] = v;
            s1 += v;
            s2 = fmaf(v, v, s2);
        }
        float t1 = 0.f, t2 = 0.f;
        #pragma unroll
        for (int k = 0; k < 4; k++){ t1 += sh[k]; t2 = fmaf(sh[k], sh[k], t2); }

        warpRed4(s1, s2, t1, t2);

        if (s > 0){
            float m2 = t1 * (1.f/Dc);
            float vr = t2 * (1.f/Dc) - m2*m2;
            float rs2 = rsqrtf(vr + EPSc);
            float4 o;
            o.x = fmaf((sh[0]-m2)*rs2, g2[0], bb2[0]);
            o.y = fmaf((sh[1]-m2)*rs2, g2[1], bb2[1]);
            o.z = fmaf((sh[2]-m2)*rs2, g2[2], bb2[2]);
            o.w = fmaf((sh[3]-m2)*rs2, g2[3], bb2[3]);
            op[(size_t)(s - 1) * 256] = o;
        }

        float m  = s1 * (1.f/Dc);
        float vr = s2 * (1.f/Dc) - m*m;
        float rs = rsqrtf(vr + EPSc);
        #pragma unroll
        for (int k = 0; k < 4; k++){
            float v = fmaf((hn[k]-m)*rs, g1[k], bb1[k]);
            hst[k] = v;
            sh[k]  = v * osd[k];
        }
        zc = zn;
    }
    {
        float t1 = 0.f, t2 = 0.f, d1 = 0.f, d2 = 0.f;
        #pragma unroll
        for (int k = 0; k < 4; k++){ t1 += sh[k]; t2 = fmaf(sh[k], sh[k], t2); }
        warpRed4(t1, t2, d1, d2);
        float m2 = t1 * (1.f/Dc);
        float vr = t2 * (1.f/Dc) - m2*m2;
        float rs2 = rsqrtf(vr + EPSc);
        float4 o;
        o.x = fmaf((sh[0]-m2)*rs2, g2[0], bb2[0]);
        o.y = fmaf((sh[1]-m2)*rs2, g2[1], bb2[1]);
        o.z = fmaf((sh[2]-m2)*rs2, g2[2], bb2[2]);
        o.w = fmaf((sh[3]-m2)*rs2, g2[3], bb2[3]);
        op[(size_t)(Sc - 1) * 256] = o;
    }
}

// ---------------- softmax over heads, scale h1 in place ----------------
__global__ void k_soft(float* __restrict__ h1, float* __restrict__ scores){
    int row = blockIdx.x;
    int t = threadIdx.x, h = t >> 5, l = t & 31;
    float* base = h1 + (size_t)row * HDc + h * Dc;
    float4 a  = ((float4*)base)[l];
    float4 vv = ((const float4*)(g_v + h * Dc))[l];
    float p = a.x*vv.x + a.y*vv.y + a.z*vv.z + a.w*vv.w;
    p = warpSum(p);
    __shared__ float lg[8];
    if (l == 0) lg[h] = p + g_c[h];
    __syncthreads();
    float mx = lg[0];
    #pragma unroll
    for (int i = 1; i < 8; i++) mx = fmaxf(mx, lg[i]);
    float den = 0.f;
    #pragma unroll
    for (int i = 0; i < 8; i++) den += __expf(lg[i] - mx);
    float sc = __expf(lg[h] - mx) / den;
    a.x *= sc; a.y *= sc; a.z *= sc; a.w *= sc;
    ((float4*)base)[l] = a;
    if (l == 0) scores[row*Hc + h] = sc;
}

// ---------------- output LayerNorm ----------------
__global__ void k_outln(float* __restrict__ out,
                        const float* __restrict__ g, const float* __restrict__ bta){
    int row = blockIdx.x;
    int t = threadIdx.x;
    float4* p = (float4*)(out + (size_t)row * Ec);
    float4 v = p[t];
    float s1 = v.x + v.y + v.z + v.w;
    float s2 = v.x*v.x + v.y*v.y + v.z*v.z + v.w*v.w;
    s1 = warpSum(s1); s2 = warpSum(s2);
    __shared__ float sh1[8], sh2[8];
    if ((t & 31) == 0){ sh1[t >> 5] = s1; sh2[t >> 5] = s2; }
    __syncthreads();
    if (t < 32){
        float a = (t < 8) ? sh1[t] : 0.f;
        float b = (t < 8) ? sh2[t] : 0.f;
        a = warpSum(a); b = warpSum(b);
        if (t == 0){ sh1[0] = a; sh2[0] = b; }
    }
    __syncthreads();
    float mean = sh1[0] * (1.f/Ec);
    float var  = sh2[0] * (1.f/Ec) - mean*mean;
    float rs = rsqrtf(var + EPSc);
    float4 gg = ((const float4*)g  )[t];
    float4 bb = ((const float4*)bta)[t];
    float4 o;
    o.x = fmaf((v.x-mean)*rs, gg.x, bb.x);
    o.y = fmaf((v.y-mean)*rs, gg.y, bb.y);
    o.z = fmaf((v.z-mean)*rs, gg.z, bb.z);
    o.w = fmaf((v.w-mean)*rs, gg.w, bb.w);
    p[t] = o;
}

// ---------------- launch ----------------
extern "C" void kernel_launch(void* const* d_in, const int* in_sizes, int n_in,
                              void* d_out, int out_size)
{
    const float* x    = (const float*)d_in[0];
    const float* Wez  = (const float*)d_in[1];
    const float* bez  = (const float*)d_in[2];
    const float* Uh   = (const float*)d_in[3];
    const float* Uz   = (const float*)d_in[4];
    const float* bu   = (const float*)d_in[5];
    const float* os   = (const float*)d_in[6];
    const float* lnsg = (const float*)d_in[7];
    const float* lnsb = (const float*)d_in[8];
    const float* ffg  = (const float*)d_in[9];
    const float* ffb  = (const float*)d_in[10];
    const float* W1   = (const float*)d_in[11];
    const float* b1   = (const float*)d_in[12];
    const float* W2   = (const float*)d_in[13];
    const float* b2   = (const float*)d_in[14];
    const float* watt = (const float*)d_in[15];
    const float* lnog = (const float*)d_in[17];
    const float* lnob = (const float*)d_in[18];
    float* out = (float*)d_out;

    float *z, *hln, *h1, *sc;
    cudaGetSymbolAddress((void**)&z,   g_z);
    cudaGetSymbolAddress((void**)&hln, g_hln);
    cudaGetSymbolAddress((void**)&h1,  g_h1);
    cudaGetSymbolAddress((void**)&sc,  g_sc);

    k_prep<<<HDc + Hc, 256>>>(W2, b2, watt);
    // GEMM1: z = tanh(x @ W_ez + b_ez)
    k_gemm_tc<0><<<dim3(HDc/128, BSc/128, 1), 256>>>(x, Ec, 0, Wez, HDc, 0,
                                                     z, HDc, 0, Ec, bez, 0, nullptr);
    k_scan<<<32, 32>>>(Uh, Uz, bu, os, lnsg, lnsb, ffg, ffb);
    // GEMM2 per head: h1 = gelu(hln @ W1[h] + b1[h])
    k_gemm_tc<1><<<dim3(1, BSc/128, Hc), 256>>>(hln, HDc, Dc, W1, Dc, (long)Dc*Dc,
                                                h1, HDc, Dc, Dc, b1, Dc, nullptr);
    k_soft<<<BSc, 256>>>(h1, sc);
    // GEMM3: out_pre = g @ W2_stacked + sum_h scores*b2[h]
    k_gemm_tc<2><<<dim3(Ec/128, BSc/128, 1), 256>>>(h1, HDc, 0, W2, Ec, 0,
                                                    out, Ec, 0, HDc, b2, 0, sc);
    k_outln<<<BSc, 256>>>(out, lnog, lnob);
}